// round 1
// baseline (speedup 1.0000x reference)
#include <cuda_runtime.h>

// Problem constants
#define B_   2
#define S_   2048
#define D_   2048
#define H_   16
#define DN   128
#define DR   64
#define DV   128
#define RQ   1536
#define RKV  512
#define DQK  192          // DN + DR
#define BS   (B_ * S_)    // 4096

// ---------------------------------------------------------------------------
// Scratch (static __device__ arrays: allocation-free per harness rules)
// ---------------------------------------------------------------------------
__device__ float g_nq [BS * RQ];          // x@w_cq -> rmsnorm (in place)
__device__ float g_qn [BS * H_ * DN];     // nq@w_dq_nope
__device__ float g_qr [BS * H_ * DR];     // nq@w_dq_rope
__device__ float g_nkv[BS * RKV];         // x@w_ckv -> rmsnorm
__device__ float g_kn [BS * H_ * DN];     // nkv@w_dk_nope
__device__ float g_vr [BS * H_ * DV];     // nkv@w_dv
__device__ float g_kr [BS * DR];          // x@w_k_rope
__device__ float g_Q  [B_ * H_ * S_ * DQK];  // [b,h,s,192]
__device__ float g_K  [B_ * H_ * S_ * DQK];  // [b,h,s,192]
__device__ float g_V  [B_ * H_ * S_ * DV];   // [b,h,s,128] pre-scaled
__device__ float g_O  [BS * H_ * DV];        // [b,s,h,128]

// ---------------------------------------------------------------------------
// Generic fp32 GEMM: C[M,N] = A[M,K] @ B[K,N], all row-major.
// 128x128 block, K-tile 8, 256 threads, 8x8 micro-tile, interleaved cols
// (i = ty + 16r, j = tx + 16c) for conflict-free LDS.
// Requires: M % 128 == 0, K % 8 == 0, N % 4 == 0. N guarded.
// ---------------------------------------------------------------------------
__global__ __launch_bounds__(256)
void gemm_kernel(const float* __restrict__ A, const float* __restrict__ B,
                 float* __restrict__ C, int M, int N, int K)
{
    __shared__ float As[8][128];
    __shared__ float Bs[8][128];

    const int tid = threadIdx.x;
    const int tx = tid & 15, ty = tid >> 4;
    const int m0 = blockIdx.y * 128;
    const int n0 = blockIdx.x * 128;

    const int am = tid >> 1;             // 0..127
    const int ak = (tid & 1) * 4;        // 0 or 4
    const int bk = tid >> 5;             // 0..7
    const int bn = (tid & 31) * 4;       // 0..124
    const bool bok = (n0 + bn) < N;

    float acc[8][8];
#pragma unroll
    for (int r = 0; r < 8; ++r)
#pragma unroll
        for (int c = 0; c < 8; ++c) acc[r][c] = 0.f;

    const float* Ap = A + (size_t)(m0 + am) * K + ak;
    const float* Bp = B + (size_t)bk * N + n0 + bn;

    for (int k0 = 0; k0 < K; k0 += 8) {
        float4 av = *(const float4*)(Ap + k0);
        As[ak + 0][am] = av.x;
        As[ak + 1][am] = av.y;
        As[ak + 2][am] = av.z;
        As[ak + 3][am] = av.w;
        float4 bv = make_float4(0.f, 0.f, 0.f, 0.f);
        if (bok) bv = *(const float4*)(Bp + (size_t)k0 * N);
        *(float4*)&Bs[bk][bn] = bv;
        __syncthreads();
#pragma unroll
        for (int k = 0; k < 8; ++k) {
            float a[8], bb[8];
#pragma unroll
            for (int r = 0; r < 8; ++r) a[r] = As[k][ty + 16 * r];
#pragma unroll
            for (int c = 0; c < 8; ++c) bb[c] = Bs[k][tx + 16 * c];
#pragma unroll
            for (int r = 0; r < 8; ++r)
#pragma unroll
                for (int c = 0; c < 8; ++c) acc[r][c] += a[r] * bb[c];
        }
        __syncthreads();
    }

#pragma unroll
    for (int r = 0; r < 8; ++r) {
        const size_t rowoff = (size_t)(m0 + ty + 16 * r) * N + n0;
#pragma unroll
        for (int c = 0; c < 8; ++c) {
            const int col = tx + 16 * c;
            if (n0 + col < N) C[rowoff + col] = acc[r][c];
        }
    }
}

// ---------------------------------------------------------------------------
// RMSNorm, in place over rows of length N. One block (256 thr) per row.
// ---------------------------------------------------------------------------
__global__ void rmsnorm_kernel(float* __restrict__ X, const float* __restrict__ w, int N)
{
    const int row = blockIdx.x;
    float* x = X + (size_t)row * N;
    __shared__ float red[256];
    float ss = 0.f;
    for (int i = threadIdx.x; i < N; i += 256) { float v = x[i]; ss += v * v; }
    red[threadIdx.x] = ss;
    __syncthreads();
    for (int s = 128; s > 0; s >>= 1) {
        if (threadIdx.x < s) red[threadIdx.x] += red[threadIdx.x + s];
        __syncthreads();
    }
    const float scale = rsqrtf(red[0] / (float)N + 1e-5f);
    for (int i = threadIdx.x; i < N; i += 256) x[i] = x[i] * scale * w[i];
}

// ---------------------------------------------------------------------------
// Build Q [b,h,s,192]: nope part copied, rope part rotated with head-h freqs.
// RoPE pairs are interleaved: (t[2i], t[2i+1]).
// ---------------------------------------------------------------------------
__global__ void build_q_kernel(const float* __restrict__ qn, const float* __restrict__ qr,
                               const float* __restrict__ fcos, const float* __restrict__ fsin,
                               float* __restrict__ Qo)
{
    const int idx = blockIdx.x * blockDim.x + threadIdx.x;
    const int total = B_ * H_ * S_ * DQK;
    if (idx >= total) return;
    const int d = idx % DQK;
    const int s = (idx / DQK) % S_;
    const int h = (idx / (DQK * S_)) % H_;
    const int b = idx / (DQK * S_ * H_);
    const int row = b * S_ + s;
    float val;
    if (d < DN) {
        val = qn[(size_t)row * (H_ * DN) + h * DN + d];
    } else {
        const int t = d - DN;
        const int i = t >> 1;
        const float* base = qr + (size_t)row * (H_ * DR) + h * DR + 2 * i;
        const float r = base[0], im = base[1];
        const float c = fcos[h * (DR / 2) + i], sn = fsin[h * (DR / 2) + i];
        val = (t & 1) ? (r * sn + im * c) : (r * c - im * sn);
    }
    Qo[idx] = val;
}

// Build K [b,h,s,192]: k_nope per-head; shared k_rope rotated per head
// (the reference's broadcast of cos[1,H,1,*] over k[b,1,s,*] expands heads).
__global__ void build_k_kernel(const float* __restrict__ kn, const float* __restrict__ kr,
                               const float* __restrict__ fcos, const float* __restrict__ fsin,
                               float* __restrict__ Ko)
{
    const int idx = blockIdx.x * blockDim.x + threadIdx.x;
    const int total = B_ * H_ * S_ * DQK;
    if (idx >= total) return;
    const int d = idx % DQK;
    const int s = (idx / DQK) % S_;
    const int h = (idx / (DQK * S_)) % H_;
    const int b = idx / (DQK * S_ * H_);
    const int row = b * S_ + s;
    float val;
    if (d < DN) {
        val = kn[(size_t)row * (H_ * DN) + h * DN + d];
    } else {
        const int t = d - DN;
        const int i = t >> 1;
        const float* base = kr + (size_t)row * DR + 2 * i;   // no head dim
        const float r = base[0], im = base[1];
        const float c = fcos[h * (DR / 2) + i], sn = fsin[h * (DR / 2) + i];
        val = (t & 1) ? (r * sn + im * c) : (r * c - im * sn);
    }
    Ko[idx] = val;
}

// Build V [b,h,s,128] with the 1/sqrt(H*DV) scale folded in.
__global__ void build_v_kernel(const float* __restrict__ vr, float* __restrict__ Vo)
{
    const int idx = blockIdx.x * blockDim.x + threadIdx.x;
    const int total = B_ * H_ * S_ * DV;
    if (idx >= total) return;
    const int d = idx % DV;
    const int s = (idx / DV) % S_;
    const int h = (idx / (DV * S_)) % H_;
    const int b = idx / (DV * S_ * H_);
    const int row = b * S_ + s;
    Vo[idx] = vr[(size_t)row * (H_ * DV) + h * DV + d] * 0.022097086912079608f; // 1/sqrt(2048)
}

// ---------------------------------------------------------------------------
// Flash attention, fp32, causal. Tiles: 64 q-rows x 64 k-cols, full D staged.
// Dynamic smem ~149 KB (1 CTA/SM). Interleaved micro-tiles keep LDS
// conflict-free (row strides 193 for Q/K, 65 for S, col index = tx + 16c).
// Grid: (S/64, H, B); q-tile index reversed so longest CTAs launch first.
// ---------------------------------------------------------------------------
#define ATT_QS 193          // padded row stride for Q/K tiles
#define ATT_SMEM_FLOATS (64*ATT_QS + 64*ATT_QS + 64*DV + 64*65 + 3*64)
#define ATT_SMEM_BYTES  (ATT_SMEM_FLOATS * 4)

__global__ __launch_bounds__(256)
void attn_kernel(const float* __restrict__ Q, const float* __restrict__ K,
                 const float* __restrict__ V, float* __restrict__ O)
{
    extern __shared__ float sm[];
    float* Qs = sm;                       // [64][193]
    float* Ks = Qs + 64 * ATT_QS;         // [64][193]
    float* Vs = Ks + 64 * ATT_QS;         // [64][128]
    float* Ss = Vs + 64 * DV;             // [64][65]
    float* m_s = Ss + 64 * 65;
    float* l_s = m_s + 64;
    float* a_s = l_s + 64;

    const int tid = threadIdx.x;
    const int tx = tid & 15, ty = tid >> 4;
    const int b = blockIdx.z, h = blockIdx.y;
    const int qt = (int)gridDim.x - 1 - (int)blockIdx.x;   // reversed: long work first
    const int q0 = qt * 64;

    const float* Qg = Q + ((size_t)(b * H_ + h) * S_ + q0) * DQK;
    const float* Kg = K + ((size_t)(b * H_ + h) * S_) * DQK;
    const float* Vg = V + ((size_t)(b * H_ + h) * S_) * DV;

    // Q tile (gmem region is contiguous 64*192 floats)
    for (int idx = tid * 4; idx < 64 * DQK; idx += 1024) {
        const float4 v = *(const float4*)(Qg + idx);
        const int r = idx / DQK, c = idx % DQK;
        float* dst = Qs + r * ATT_QS + c;
        dst[0] = v.x; dst[1] = v.y; dst[2] = v.z; dst[3] = v.w;
    }
    if (tid < 64) { m_s[tid] = -1e30f; l_s[tid] = 0.f; }

    float acc[4][8];
#pragma unroll
    for (int r = 0; r < 4; ++r)
#pragma unroll
        for (int c = 0; c < 8; ++c) acc[r][c] = 0.f;

    const float scale = 0.07216878364870322f;   // 1/sqrt(192)

    for (int kt = 0; kt <= qt; ++kt) {
        const int k0 = kt * 64;
        __syncthreads();   // protect Ks/Vs reuse (and Q-load on first iter)
        for (int idx = tid * 4; idx < 64 * DQK; idx += 1024) {
            const float4 v = *(const float4*)(Kg + (size_t)k0 * DQK + idx);
            const int r = idx / DQK, c = idx % DQK;
            float* dst = Ks + r * ATT_QS + c;
            dst[0] = v.x; dst[1] = v.y; dst[2] = v.z; dst[3] = v.w;
        }
        for (int idx = tid * 4; idx < 64 * DV; idx += 1024)
            *(float4*)(Vs + idx) = *(const float4*)(Vg + (size_t)k0 * DV + idx);
        __syncthreads();

        // ---- S = Q K^T ----
        float sc[4][4];
#pragma unroll
        for (int r = 0; r < 4; ++r)
#pragma unroll
            for (int c = 0; c < 4; ++c) sc[r][c] = 0.f;

#pragma unroll 8
        for (int d = 0; d < DQK; ++d) {
            float a[4], bb[4];
#pragma unroll
            for (int r = 0; r < 4; ++r) a[r] = Qs[(ty + 16 * r) * ATT_QS + d];
#pragma unroll
            for (int c = 0; c < 4; ++c) bb[c] = Ks[(tx + 16 * c) * ATT_QS + d];
#pragma unroll
            for (int r = 0; r < 4; ++r)
#pragma unroll
                for (int c = 0; c < 4; ++c) sc[r][c] += a[r] * bb[c];
        }
#pragma unroll
        for (int r = 0; r < 4; ++r)
#pragma unroll
            for (int c = 0; c < 4; ++c) {
                const int qi = q0 + ty + 16 * r;
                const int ki = k0 + tx + 16 * c;
                float v = sc[r][c] * scale;
                if (ki > qi) v = -1e30f;
                Ss[(ty + 16 * r) * 65 + tx + 16 * c] = v;
            }
        __syncthreads();

        // ---- online softmax (one thread per row) ----
        if (tid < 64) {
            float* row = Ss + tid * 65;
            const float mold = m_s[tid];
            float mx = mold;
#pragma unroll 8
            for (int j = 0; j < 64; ++j) mx = fmaxf(mx, row[j]);
            const float alpha = __expf(mold - mx);
            float l = l_s[tid] * alpha;
#pragma unroll 8
            for (int j = 0; j < 64; ++j) { const float p = __expf(row[j] - mx); row[j] = p; l += p; }
            m_s[tid] = mx; l_s[tid] = l; a_s[tid] = alpha;
        }
        __syncthreads();

        // ---- O = alpha*O + P V ----
        float al[4];
#pragma unroll
        for (int r = 0; r < 4; ++r) al[r] = a_s[ty + 16 * r];
#pragma unroll
        for (int r = 0; r < 4; ++r)
#pragma unroll
            for (int c = 0; c < 8; ++c) acc[r][c] *= al[r];

#pragma unroll 2
        for (int j = 0; j < 64; ++j) {
            float p[4], v[8];
#pragma unroll
            for (int r = 0; r < 4; ++r) p[r] = Ss[(ty + 16 * r) * 65 + j];
#pragma unroll
            for (int c = 0; c < 8; ++c) v[c] = Vs[j * DV + tx + 16 * c];
#pragma unroll
            for (int r = 0; r < 4; ++r)
#pragma unroll
                for (int c = 0; c < 8; ++c) acc[r][c] += p[r] * v[c];
        }
    }
    __syncthreads();

    // normalize + store to [b, s, h, 128]
#pragma unroll
    for (int r = 0; r < 4; ++r) {
        const int s = q0 + ty + 16 * r;
        const float linv = 1.f / l_s[ty + 16 * r];
        float* dst = g_O + (((size_t)(b * S_ + s)) * H_ + h) * DV;
#pragma unroll
        for (int c = 0; c < 8; ++c) dst[tx + 16 * c] = acc[r][c] * linv;
    }
    (void)O;
}

// ---------------------------------------------------------------------------
// Host launcher
// ---------------------------------------------------------------------------
extern "C" void kernel_launch(void* const* d_in, const int* in_sizes, int n_in,
                              void* d_out, int out_size)
{
    (void)in_sizes; (void)n_in; (void)out_size;
    const float* x        = (const float*)d_in[0];
    /* d_in[1] = mask: all zeros and unused by the reference */
    const float* fcos     = (const float*)d_in[2];
    const float* fsin     = (const float*)d_in[3];
    const float* w_cq     = (const float*)d_in[4];
    const float* q_norm_w = (const float*)d_in[5];
    const float* w_dq_n   = (const float*)d_in[6];
    const float* w_dq_r   = (const float*)d_in[7];
    const float* w_ckv    = (const float*)d_in[8];
    const float* kv_norm_w= (const float*)d_in[9];
    const float* w_dk_n   = (const float*)d_in[10];
    const float* w_dv     = (const float*)d_in[11];
    const float* w_k_rope = (const float*)d_in[12];
    const float* w_proj   = (const float*)d_in[13];
    float* out = (float*)d_out;

    float *nq, *qn, *qr, *nkv, *kn, *vr, *kr, *Q, *K, *V, *O;
    cudaGetSymbolAddress((void**)&nq,  g_nq);
    cudaGetSymbolAddress((void**)&qn,  g_qn);
    cudaGetSymbolAddress((void**)&qr,  g_qr);
    cudaGetSymbolAddress((void**)&nkv, g_nkv);
    cudaGetSymbolAddress((void**)&kn,  g_kn);
    cudaGetSymbolAddress((void**)&vr,  g_vr);
    cudaGetSymbolAddress((void**)&kr,  g_kr);
    cudaGetSymbolAddress((void**)&Q,   g_Q);
    cudaGetSymbolAddress((void**)&K,   g_K);
    cudaGetSymbolAddress((void**)&V,   g_V);
    cudaGetSymbolAddress((void**)&O,   g_O);

    // --- projections + norms ---
    gemm_kernel<<<dim3(RQ / 128, BS / 128), 256>>>(x, w_cq, nq, BS, RQ, D_);
    rmsnorm_kernel<<<BS, 256>>>(nq, q_norm_w, RQ);
    gemm_kernel<<<dim3((H_ * DN) / 128, BS / 128), 256>>>(nq, w_dq_n, qn, BS, H_ * DN, RQ);
    gemm_kernel<<<dim3((H_ * DR) / 128, BS / 128), 256>>>(nq, w_dq_r, qr, BS, H_ * DR, RQ);
    gemm_kernel<<<dim3(RKV / 128, BS / 128), 256>>>(x, w_ckv, nkv, BS, RKV, D_);
    rmsnorm_kernel<<<BS, 256>>>(nkv, kv_norm_w, RKV);
    gemm_kernel<<<dim3((H_ * DN) / 128, BS / 128), 256>>>(nkv, w_dk_n, kn, BS, H_ * DN, RKV);
    gemm_kernel<<<dim3((H_ * DV) / 128, BS / 128), 256>>>(nkv, w_dv, vr, BS, H_ * DV, RKV);
    gemm_kernel<<<dim3(1, BS / 128), 256>>>(x, w_k_rope, kr, BS, DR, D_);

    // --- assemble Q/K/V with RoPE + scaling ---
    {
        const int tq = B_ * H_ * S_ * DQK;
        build_q_kernel<<<(tq + 255) / 256, 256>>>(qn, qr, fcos, fsin, Q);
        build_k_kernel<<<(tq + 255) / 256, 256>>>(kn, kr, fcos, fsin, K);
        const int tv = B_ * H_ * S_ * DV;
        build_v_kernel<<<(tv + 255) / 256, 256>>>(vr, V);
    }

    // --- flash attention ---
    cudaFuncSetAttribute(attn_kernel, cudaFuncAttributeMaxDynamicSharedMemorySize, ATT_SMEM_BYTES);
    attn_kernel<<<dim3(S_ / 64, H_, B_), 256, ATT_SMEM_BYTES>>>(Q, K, V, O);

    // --- output projection ---
    gemm_kernel<<<dim3(D_ / 128, BS / 128), 256>>>(O, w_proj, out, BS, D_, D_);
}

// round 2
// speedup vs baseline: 1.9454x; 1.9454x over previous
#include <cuda_runtime.h>
#include <cstdint>

// Problem constants
#define B_   2
#define S_   2048
#define D_   2048
#define H_   16
#define DN   128
#define DR   64
#define DV   128
#define RQ   1536
#define RKV  512
#define DQK  192          // DN + DR
#define BS   (B_ * S_)    // 4096

// ---------------------------------------------------------------------------
// Scratch
// ---------------------------------------------------------------------------
__device__ float g_nq [BS * RQ];
__device__ float g_qn [BS * H_ * DN];
__device__ float g_qr [BS * H_ * DR];
__device__ float g_nkv[BS * RKV];
__device__ float g_kn [BS * H_ * DN];
__device__ float g_vr [BS * H_ * DV];
__device__ float g_kr [BS * DR];
__device__ float g_Q  [B_ * H_ * S_ * DQK];
__device__ float g_K  [B_ * H_ * S_ * DQK];
__device__ float g_V  [B_ * H_ * S_ * DV];
__device__ float g_O  [BS * H_ * DV];

// ---------------------------------------------------------------------------
// tf32 tensor-core GEMM: C[M,N] = A[M,K] @ B[K,N], row-major.
// 128x128 tile, BK=16, cp.async double buffer, 8 warps (4x2), each warp 32x64
// via m16n8k8 tf32 mma. Requires M%128==0, K%16==0. N guarded (zero-filled).
// ---------------------------------------------------------------------------
#define ASTRIDE 20    // [m][k] rows padded 16->20: conflict-free quad octets
#define BSTRIDE 136   // [k][n] rows padded 128->136 (136%32==8): conflict-free

__device__ __forceinline__ void cp_async16(uint32_t dst, const void* src, int src_bytes) {
    asm volatile("cp.async.ca.shared.global [%0], [%1], 16, %2;\n"
                 :: "r"(dst), "l"(src), "r"(src_bytes));
}
__device__ __forceinline__ uint32_t f2tf32(float f) {
    uint32_t r;
    asm("cvt.rna.tf32.f32 %0, %1;" : "=r"(r) : "f"(f));
    return r;
}
__device__ __forceinline__ void mma_tf32(float* c, const uint32_t* a, const uint32_t* b) {
    asm volatile(
        "mma.sync.aligned.m16n8k8.row.col.f32.tf32.tf32.f32 "
        "{%0,%1,%2,%3}, {%4,%5,%6,%7}, {%8,%9}, {%0,%1,%2,%3};"
        : "+f"(c[0]), "+f"(c[1]), "+f"(c[2]), "+f"(c[3])
        : "r"(a[0]), "r"(a[1]), "r"(a[2]), "r"(a[3]), "r"(b[0]), "r"(b[1]));
}

__global__ __launch_bounds__(256)
void gemm_tf32_kernel(const float* __restrict__ A, const float* __restrict__ B,
                      float* __restrict__ C, int M, int N, int K)
{
    __shared__ float As[2][128][ASTRIDE];
    __shared__ float Bs[2][16][BSTRIDE];

    const int tid  = threadIdx.x;
    const int lane = tid & 31;
    const int wid  = tid >> 5;
    const int wm   = wid & 3;          // warp row (32 m-rows)
    const int wn   = wid >> 2;         // warp col (64 n-cols)
    const int grp  = lane >> 2;        // 0..7
    const int quad = lane & 3;         // 0..3

    const int m0 = blockIdx.y * 128;
    const int n0 = blockIdx.x * 128;

    // A tile: 128 rows x 16 cols = 512 float4; thread handles idx, idx+256
    const int ar0 = tid >> 2;                 // via idx=tid: row=tid/4
    const int ac0 = (tid & 3) * 4;
    // B tile: 16 rows x 128 cols = 512 float4
    const int br0 = tid >> 5;                 // idx=tid: row=tid/32
    const int bc0 = (tid & 31) * 4;

    uint32_t sAs, sBs;
    { uint32_t base; asm("{ .reg .u64 t; cvta.to.shared.u64 t, %1; cvt.u32.u64 %0, t; }"
                         : "=r"(base) : "l"((void*)&As[0][0][0])); sAs = base; }
    { uint32_t base; asm("{ .reg .u64 t; cvta.to.shared.u64 t, %1; cvt.u32.u64 %0, t; }"
                         : "=r"(base) : "l"((void*)&Bs[0][0][0])); sBs = base; }

    const int ntiles = K / 16;

    auto load_stage = [&](int kt, int s) {
        const int k0 = kt * 16;
        // A: rows ar0, ar0+64 ; 4 cols of float4 split by thread
        {
            const float* src = A + (size_t)(m0 + ar0) * K + k0 + ac0;
            uint32_t dst = sAs + ((s * 128 + ar0) * ASTRIDE + ac0) * 4;
            cp_async16(dst, src, 16);
            const float* src2 = src + (size_t)64 * K;
            uint32_t dst2 = dst + 64 * ASTRIDE * 4;
            cp_async16(dst2, src2, 16);
        }
        // B: rows br0, br0+8
        {
            const int col = n0 + bc0;
            const int ok = (col < N) ? 16 : 0;
            const float* src = B + (size_t)(k0 + br0) * N + (ok ? col : 0);
            uint32_t dst = sBs + ((s * 16 + br0) * BSTRIDE + bc0) * 4;
            cp_async16(dst, src, ok);
            const float* src2 = src + (size_t)8 * N;
            uint32_t dst2 = dst + 8 * BSTRIDE * 4;
            cp_async16(dst2, src2, ok);
        }
    };

    float acc[2][8][4];
#pragma unroll
    for (int mt = 0; mt < 2; ++mt)
#pragma unroll
        for (int nt = 0; nt < 8; ++nt)
#pragma unroll
            for (int i = 0; i < 4; ++i) acc[mt][nt][i] = 0.f;

    load_stage(0, 0);
    asm volatile("cp.async.commit_group;\n");

    for (int kt = 0; kt < ntiles; ++kt) {
        const int s = kt & 1;
        if (kt + 1 < ntiles) load_stage(kt + 1, (kt + 1) & 1);
        asm volatile("cp.async.commit_group;\n");
        asm volatile("cp.async.wait_group 1;\n");
        __syncthreads();

#pragma unroll
        for (int kk = 0; kk < 16; kk += 8) {
            uint32_t afr[2][4];
#pragma unroll
            for (int mt = 0; mt < 2; ++mt) {
                const int mrow = wm * 32 + mt * 16 + grp;
                afr[mt][0] = f2tf32(As[s][mrow    ][kk + quad    ]);
                afr[mt][1] = f2tf32(As[s][mrow + 8][kk + quad    ]);
                afr[mt][2] = f2tf32(As[s][mrow    ][kk + quad + 4]);
                afr[mt][3] = f2tf32(As[s][mrow + 8][kk + quad + 4]);
            }
            uint32_t bfr[8][2];
#pragma unroll
            for (int nt = 0; nt < 8; ++nt) {
                const int ncol = wn * 64 + nt * 8 + grp;
                bfr[nt][0] = f2tf32(Bs[s][kk + quad    ][ncol]);
                bfr[nt][1] = f2tf32(Bs[s][kk + quad + 4][ncol]);
            }
#pragma unroll
            for (int mt = 0; mt < 2; ++mt)
#pragma unroll
                for (int nt = 0; nt < 8; ++nt)
                    mma_tf32(acc[mt][nt], afr[mt], bfr[nt]);
        }
        __syncthreads();
    }
    asm volatile("cp.async.wait_group 0;\n");

    // Epilogue: c0,c1 at (row, 2q), (row, 2q+1); c2,c3 at row+8
#pragma unroll
    for (int mt = 0; mt < 2; ++mt) {
        const int mrow = m0 + wm * 32 + mt * 16 + grp;
#pragma unroll
        for (int nt = 0; nt < 8; ++nt) {
            const int ncol = n0 + wn * 64 + nt * 8 + quad * 2;
            if (ncol < N) {
                float2 v0 = make_float2(acc[mt][nt][0], acc[mt][nt][1]);
                float2 v1 = make_float2(acc[mt][nt][2], acc[mt][nt][3]);
                *(float2*)(C + (size_t)mrow * N + ncol) = v0;
                *(float2*)(C + (size_t)(mrow + 8) * N + ncol) = v1;
            }
        }
    }
}

// ---------------------------------------------------------------------------
// RMSNorm, in place. One block (256 thr) per row.
// ---------------------------------------------------------------------------
__global__ void rmsnorm_kernel(float* __restrict__ X, const float* __restrict__ w, int N)
{
    const int row = blockIdx.x;
    float* x = X + (size_t)row * N;
    __shared__ float red[256];
    float ss = 0.f;
    for (int i = threadIdx.x; i < N; i += 256) { float v = x[i]; ss += v * v; }
    red[threadIdx.x] = ss;
    __syncthreads();
    for (int s = 128; s > 0; s >>= 1) {
        if (threadIdx.x < s) red[threadIdx.x] += red[threadIdx.x + s];
        __syncthreads();
    }
    const float scale = rsqrtf(red[0] / (float)N + 1e-5f);
    for (int i = threadIdx.x; i < N; i += 256) x[i] = x[i] * scale * w[i];
}

// ---------------------------------------------------------------------------
// Build Q/K/V (RoPE fused), unchanged from R1.
// ---------------------------------------------------------------------------
__global__ void build_q_kernel(const float* __restrict__ qn, const float* __restrict__ qr,
                               const float* __restrict__ fcos, const float* __restrict__ fsin,
                               float* __restrict__ Qo)
{
    const int idx = blockIdx.x * blockDim.x + threadIdx.x;
    const int total = B_ * H_ * S_ * DQK;
    if (idx >= total) return;
    const int d = idx % DQK;
    const int s = (idx / DQK) % S_;
    const int h = (idx / (DQK * S_)) % H_;
    const int b = idx / (DQK * S_ * H_);
    const int row = b * S_ + s;
    float val;
    if (d < DN) {
        val = qn[(size_t)row * (H_ * DN) + h * DN + d];
    } else {
        const int t = d - DN;
        const int i = t >> 1;
        const float* base = qr + (size_t)row * (H_ * DR) + h * DR + 2 * i;
        const float r = base[0], im = base[1];
        const float c = fcos[h * (DR / 2) + i], sn = fsin[h * (DR / 2) + i];
        val = (t & 1) ? (r * sn + im * c) : (r * c - im * sn);
    }
    Qo[idx] = val;
}

__global__ void build_k_kernel(const float* __restrict__ kn, const float* __restrict__ kr,
                               const float* __restrict__ fcos, const float* __restrict__ fsin,
                               float* __restrict__ Ko)
{
    const int idx = blockIdx.x * blockDim.x + threadIdx.x;
    const int total = B_ * H_ * S_ * DQK;
    if (idx >= total) return;
    const int d = idx % DQK;
    const int s = (idx / DQK) % S_;
    const int h = (idx / (DQK * S_)) % H_;
    const int b = idx / (DQK * S_ * H_);
    const int row = b * S_ + s;
    float val;
    if (d < DN) {
        val = kn[(size_t)row * (H_ * DN) + h * DN + d];
    } else {
        const int t = d - DN;
        const int i = t >> 1;
        const float* base = kr + (size_t)row * DR + 2 * i;
        const float r = base[0], im = base[1];
        const float c = fcos[h * (DR / 2) + i], sn = fsin[h * (DR / 2) + i];
        val = (t & 1) ? (r * sn + im * c) : (r * c - im * sn);
    }
    Ko[idx] = val;
}

__global__ void build_v_kernel(const float* __restrict__ vr, float* __restrict__ Vo)
{
    const int idx = blockIdx.x * blockDim.x + threadIdx.x;
    const int total = B_ * H_ * S_ * DV;
    if (idx >= total) return;
    const int d = idx % DV;
    const int s = (idx / DV) % S_;
    const int h = (idx / (DV * S_)) % H_;
    const int b = idx / (DV * S_ * H_);
    const int row = b * S_ + s;
    Vo[idx] = vr[(size_t)row * (H_ * DV) + h * DV + d] * 0.022097086912079608f;
}

// ---------------------------------------------------------------------------
// Flash attention, fp32, causal (unchanged from R1).
// ---------------------------------------------------------------------------
#define ATT_QS 193
#define ATT_SMEM_FLOATS (64*ATT_QS + 64*ATT_QS + 64*DV + 64*65 + 3*64)
#define ATT_SMEM_BYTES  (ATT_SMEM_FLOATS * 4)

__global__ __launch_bounds__(256)
void attn_kernel(const float* __restrict__ Q, const float* __restrict__ K,
                 const float* __restrict__ V, float* __restrict__ O)
{
    extern __shared__ float sm[];
    float* Qs = sm;
    float* Ks = Qs + 64 * ATT_QS;
    float* Vs = Ks + 64 * ATT_QS;
    float* Ss = Vs + 64 * DV;
    float* m_s = Ss + 64 * 65;
    float* l_s = m_s + 64;
    float* a_s = l_s + 64;

    const int tid = threadIdx.x;
    const int tx = tid & 15, ty = tid >> 4;
    const int b = blockIdx.z, h = blockIdx.y;
    const int qt = (int)gridDim.x - 1 - (int)blockIdx.x;
    const int q0 = qt * 64;

    const float* Qg = Q + ((size_t)(b * H_ + h) * S_ + q0) * DQK;
    const float* Kg = K + ((size_t)(b * H_ + h) * S_) * DQK;
    const float* Vg = V + ((size_t)(b * H_ + h) * S_) * DV;

    for (int idx = tid * 4; idx < 64 * DQK; idx += 1024) {
        const float4 v = *(const float4*)(Qg + idx);
        const int r = idx / DQK, c = idx % DQK;
        float* dst = Qs + r * ATT_QS + c;
        dst[0] = v.x; dst[1] = v.y; dst[2] = v.z; dst[3] = v.w;
    }
    if (tid < 64) { m_s[tid] = -1e30f; l_s[tid] = 0.f; }

    float acc[4][8];
#pragma unroll
    for (int r = 0; r < 4; ++r)
#pragma unroll
        for (int c = 0; c < 8; ++c) acc[r][c] = 0.f;

    const float scale = 0.07216878364870322f;

    for (int kt = 0; kt <= qt; ++kt) {
        const int k0 = kt * 64;
        __syncthreads();
        for (int idx = tid * 4; idx < 64 * DQK; idx += 1024) {
            const float4 v = *(const float4*)(Kg + (size_t)k0 * DQK + idx);
            const int r = idx / DQK, c = idx % DQK;
            float* dst = Ks + r * ATT_QS + c;
            dst[0] = v.x; dst[1] = v.y; dst[2] = v.z; dst[3] = v.w;
        }
        for (int idx = tid * 4; idx < 64 * DV; idx += 1024)
            *(float4*)(Vs + idx) = *(const float4*)(Vg + (size_t)k0 * DV + idx);
        __syncthreads();

        float sc[4][4];
#pragma unroll
        for (int r = 0; r < 4; ++r)
#pragma unroll
            for (int c = 0; c < 4; ++c) sc[r][c] = 0.f;

#pragma unroll 8
        for (int d = 0; d < DQK; ++d) {
            float a[4], bb[4];
#pragma unroll
            for (int r = 0; r < 4; ++r) a[r] = Qs[(ty + 16 * r) * ATT_QS + d];
#pragma unroll
            for (int c = 0; c < 4; ++c) bb[c] = Ks[(tx + 16 * c) * ATT_QS + d];
#pragma unroll
            for (int r = 0; r < 4; ++r)
#pragma unroll
                for (int c = 0; c < 4; ++c) sc[r][c] += a[r] * bb[c];
        }
#pragma unroll
        for (int r = 0; r < 4; ++r)
#pragma unroll
            for (int c = 0; c < 4; ++c) {
                const int qi = q0 + ty + 16 * r;
                const int ki = k0 + tx + 16 * c;
                float v = sc[r][c] * scale;
                if (ki > qi) v = -1e30f;
                Ss[(ty + 16 * r) * 65 + tx + 16 * c] = v;
            }
        __syncthreads();

        if (tid < 64) {
            float* row = Ss + tid * 65;
            const float mold = m_s[tid];
            float mx = mold;
#pragma unroll 8
            for (int j = 0; j < 64; ++j) mx = fmaxf(mx, row[j]);
            const float alpha = __expf(mold - mx);
            float l = l_s[tid] * alpha;
#pragma unroll 8
            for (int j = 0; j < 64; ++j) { const float p = __expf(row[j] - mx); row[j] = p; l += p; }
            m_s[tid] = mx; l_s[tid] = l; a_s[tid] = alpha;
        }
        __syncthreads();

        float al[4];
#pragma unroll
        for (int r = 0; r < 4; ++r) al[r] = a_s[ty + 16 * r];
#pragma unroll
        for (int r = 0; r < 4; ++r)
#pragma unroll
            for (int c = 0; c < 8; ++c) acc[r][c] *= al[r];

#pragma unroll 2
        for (int j = 0; j < 64; ++j) {
            float p[4], v[8];
#pragma unroll
            for (int r = 0; r < 4; ++r) p[r] = Ss[(ty + 16 * r) * 65 + j];
#pragma unroll
            for (int c = 0; c < 8; ++c) v[c] = Vs[j * DV + tx + 16 * c];
#pragma unroll
            for (int r = 0; r < 4; ++r)
#pragma unroll
                for (int c = 0; c < 8; ++c) acc[r][c] += p[r] * v[c];
        }
    }
    __syncthreads();

#pragma unroll
    for (int r = 0; r < 4; ++r) {
        const int s = q0 + ty + 16 * r;
        const float linv = 1.f / l_s[ty + 16 * r];
        float* dst = g_O + (((size_t)(b * S_ + s)) * H_ + h) * DV;
#pragma unroll
        for (int c = 0; c < 8; ++c) dst[tx + 16 * c] = acc[r][c] * linv;
    }
    (void)O;
}

// ---------------------------------------------------------------------------
// Host launcher
// ---------------------------------------------------------------------------
extern "C" void kernel_launch(void* const* d_in, const int* in_sizes, int n_in,
                              void* d_out, int out_size)
{
    (void)in_sizes; (void)n_in; (void)out_size;
    const float* x        = (const float*)d_in[0];
    const float* fcos     = (const float*)d_in[2];
    const float* fsin     = (const float*)d_in[3];
    const float* w_cq     = (const float*)d_in[4];
    const float* q_norm_w = (const float*)d_in[5];
    const float* w_dq_n   = (const float*)d_in[6];
    const float* w_dq_r   = (const float*)d_in[7];
    const float* w_ckv    = (const float*)d_in[8];
    const float* kv_norm_w= (const float*)d_in[9];
    const float* w_dk_n   = (const float*)d_in[10];
    const float* w_dv     = (const float*)d_in[11];
    const float* w_k_rope = (const float*)d_in[12];
    const float* w_proj   = (const float*)d_in[13];
    float* out = (float*)d_out;

    float *nq, *qn, *qr, *nkv, *kn, *vr, *kr, *Q, *K, *V, *O;
    cudaGetSymbolAddress((void**)&nq,  g_nq);
    cudaGetSymbolAddress((void**)&qn,  g_qn);
    cudaGetSymbolAddress((void**)&qr,  g_qr);
    cudaGetSymbolAddress((void**)&nkv, g_nkv);
    cudaGetSymbolAddress((void**)&kn,  g_kn);
    cudaGetSymbolAddress((void**)&vr,  g_vr);
    cudaGetSymbolAddress((void**)&kr,  g_kr);
    cudaGetSymbolAddress((void**)&Q,   g_Q);
    cudaGetSymbolAddress((void**)&K,   g_K);
    cudaGetSymbolAddress((void**)&V,   g_V);
    cudaGetSymbolAddress((void**)&O,   g_O);

    // --- projections + norms (tf32 tensor cores) ---
    gemm_tf32_kernel<<<dim3(RQ / 128, BS / 128), 256>>>(x, w_cq, nq, BS, RQ, D_);
    rmsnorm_kernel<<<BS, 256>>>(nq, q_norm_w, RQ);
    gemm_tf32_kernel<<<dim3((H_ * DN) / 128, BS / 128), 256>>>(nq, w_dq_n, qn, BS, H_ * DN, RQ);
    gemm_tf32_kernel<<<dim3((H_ * DR) / 128, BS / 128), 256>>>(nq, w_dq_r, qr, BS, H_ * DR, RQ);
    gemm_tf32_kernel<<<dim3(RKV / 128, BS / 128), 256>>>(x, w_ckv, nkv, BS, RKV, D_);
    rmsnorm_kernel<<<BS, 256>>>(nkv, kv_norm_w, RKV);
    gemm_tf32_kernel<<<dim3((H_ * DN) / 128, BS / 128), 256>>>(nkv, w_dk_n, kn, BS, H_ * DN, RKV);
    gemm_tf32_kernel<<<dim3((H_ * DV) / 128, BS / 128), 256>>>(nkv, w_dv, vr, BS, H_ * DV, RKV);
    gemm_tf32_kernel<<<dim3(1, BS / 128), 256>>>(x, w_k_rope, kr, BS, DR, D_);

    // --- assemble Q/K/V ---
    {
        const int tq = B_ * H_ * S_ * DQK;
        build_q_kernel<<<(tq + 255) / 256, 256>>>(qn, qr, fcos, fsin, Q);
        build_k_kernel<<<(tq + 255) / 256, 256>>>(kn, kr, fcos, fsin, K);
        const int tv = B_ * H_ * S_ * DV;
        build_v_kernel<<<(tv + 255) / 256, 256>>>(vr, V);
    }

    // --- flash attention (fp32) ---
    cudaFuncSetAttribute(attn_kernel, cudaFuncAttributeMaxDynamicSharedMemorySize, ATT_SMEM_BYTES);
    attn_kernel<<<dim3(S_ / 64, H_, B_), 256, ATT_SMEM_BYTES>>>(Q, K, V, O);

    // --- output projection ---
    gemm_tf32_kernel<<<dim3(D_ / 128, BS / 128), 256>>>(O, w_proj, out, BS, D_, D_);
}

// round 12
// speedup vs baseline: 2.7276x; 1.4021x over previous
#include <cuda_runtime.h>
#include <cstdint>

// Problem constants
#define B_   2
#define S_   2048
#define D_   2048
#define H_   16
#define DN   128
#define DR   64
#define DV   128
#define RQ   1536
#define RKV  512
#define DQK  192
#define BS   (B_ * S_)

// ---------------------------------------------------------------------------
// Scratch
// ---------------------------------------------------------------------------
__device__ float g_nq [BS * RQ];
__device__ float g_qn [BS * H_ * DN];
__device__ float g_qr [BS * H_ * DR];
__device__ float g_nkv[BS * RKV];
__device__ float g_kn [BS * H_ * DN];
__device__ float g_vr [BS * H_ * DV];
__device__ float g_kr [BS * DR];
__device__ float g_Q  [B_ * H_ * S_ * DQK];
__device__ float g_K  [B_ * H_ * S_ * DQK];
__device__ float g_V  [B_ * H_ * S_ * DV];
__device__ float g_O  [BS * H_ * DV];

// ---------------------------------------------------------------------------
// tf32 helpers
// ---------------------------------------------------------------------------
__device__ __forceinline__ void cp_async16(uint32_t dst, const void* src, int src_bytes) {
    asm volatile("cp.async.ca.shared.global [%0], [%1], 16, %2;\n"
                 :: "r"(dst), "l"(src), "r"(src_bytes));
}
__device__ __forceinline__ uint32_t f2tf32(float f) {
    uint32_t r;
    asm("cvt.rna.tf32.f32 %0, %1;" : "=r"(r) : "f"(f));
    return r;
}
__device__ __forceinline__ void mma_tf32(float* c, const uint32_t* a, const uint32_t* b) {
    asm volatile(
        "mma.sync.aligned.m16n8k8.row.col.f32.tf32.tf32.f32 "
        "{%0,%1,%2,%3}, {%4,%5,%6,%7}, {%8,%9}, {%0,%1,%2,%3};"
        : "+f"(c[0]), "+f"(c[1]), "+f"(c[2]), "+f"(c[3])
        : "r"(a[0]), "r"(a[1]), "r"(a[2]), "r"(a[3]), "r"(b[0]), "r"(b[1]));
}

// ---------------------------------------------------------------------------
// tf32 tensor-core GEMM (unchanged from R2)
// ---------------------------------------------------------------------------
#define ASTRIDE 20
#define BSTRIDE 136

__global__ __launch_bounds__(256)
void gemm_tf32_kernel(const float* __restrict__ A, const float* __restrict__ B,
                      float* __restrict__ C, int M, int N, int K)
{
    __shared__ float As[2][128][ASTRIDE];
    __shared__ float Bs[2][16][BSTRIDE];

    const int tid  = threadIdx.x;
    const int lane = tid & 31;
    const int wid  = tid >> 5;
    const int wm   = wid & 3;
    const int wn   = wid >> 2;
    const int grp  = lane >> 2;
    const int quad = lane & 3;

    const int m0 = blockIdx.y * 128;
    const int n0 = blockIdx.x * 128;

    const int ar0 = tid >> 2;
    const int ac0 = (tid & 3) * 4;
    const int br0 = tid >> 5;
    const int bc0 = (tid & 31) * 4;

    uint32_t sAs, sBs;
    { uint32_t base; asm("{ .reg .u64 t; cvta.to.shared.u64 t, %1; cvt.u32.u64 %0, t; }"
                         : "=r"(base) : "l"((void*)&As[0][0][0])); sAs = base; }
    { uint32_t base; asm("{ .reg .u64 t; cvta.to.shared.u64 t, %1; cvt.u32.u64 %0, t; }"
                         : "=r"(base) : "l"((void*)&Bs[0][0][0])); sBs = base; }

    const int ntiles = K / 16;

    auto load_stage = [&](int kt, int s) {
        const int k0 = kt * 16;
        {
            const float* src = A + (size_t)(m0 + ar0) * K + k0 + ac0;
            uint32_t dst = sAs + ((s * 128 + ar0) * ASTRIDE + ac0) * 4;
            cp_async16(dst, src, 16);
            const float* src2 = src + (size_t)64 * K;
            uint32_t dst2 = dst + 64 * ASTRIDE * 4;
            cp_async16(dst2, src2, 16);
        }
        {
            const int col = n0 + bc0;
            const int ok = (col < N) ? 16 : 0;
            const float* src = B + (size_t)(k0 + br0) * N + (ok ? col : 0);
            uint32_t dst = sBs + ((s * 16 + br0) * BSTRIDE + bc0) * 4;
            cp_async16(dst, src, ok);
            const float* src2 = src + (size_t)8 * N;
            uint32_t dst2 = dst + 8 * BSTRIDE * 4;
            cp_async16(dst2, src2, ok);
        }
    };

    float acc[2][8][4];
#pragma unroll
    for (int mt = 0; mt < 2; ++mt)
#pragma unroll
        for (int nt = 0; nt < 8; ++nt)
#pragma unroll
            for (int i = 0; i < 4; ++i) acc[mt][nt][i] = 0.f;

    load_stage(0, 0);
    asm volatile("cp.async.commit_group;\n");

    for (int kt = 0; kt < ntiles; ++kt) {
        const int s = kt & 1;
        if (kt + 1 < ntiles) load_stage(kt + 1, (kt + 1) & 1);
        asm volatile("cp.async.commit_group;\n");
        asm volatile("cp.async.wait_group 1;\n");
        __syncthreads();

#pragma unroll
        for (int kk = 0; kk < 16; kk += 8) {
            uint32_t afr[2][4];
#pragma unroll
            for (int mt = 0; mt < 2; ++mt) {
                const int mrow = wm * 32 + mt * 16 + grp;
                afr[mt][0] = f2tf32(As[s][mrow    ][kk + quad    ]);
                afr[mt][1] = f2tf32(As[s][mrow + 8][kk + quad    ]);
                afr[mt][2] = f2tf32(As[s][mrow    ][kk + quad + 4]);
                afr[mt][3] = f2tf32(As[s][mrow + 8][kk + quad + 4]);
            }
            uint32_t bfr[8][2];
#pragma unroll
            for (int nt = 0; nt < 8; ++nt) {
                const int ncol = wn * 64 + nt * 8 + grp;
                bfr[nt][0] = f2tf32(Bs[s][kk + quad    ][ncol]);
                bfr[nt][1] = f2tf32(Bs[s][kk + quad + 4][ncol]);
            }
#pragma unroll
            for (int mt = 0; mt < 2; ++mt)
#pragma unroll
                for (int nt = 0; nt < 8; ++nt)
                    mma_tf32(acc[mt][nt], afr[mt], bfr[nt]);
        }
        __syncthreads();
    }
    asm volatile("cp.async.wait_group 0;\n");

#pragma unroll
    for (int mt = 0; mt < 2; ++mt) {
        const int mrow = m0 + wm * 32 + mt * 16 + grp;
#pragma unroll
        for (int nt = 0; nt < 8; ++nt) {
            const int ncol = n0 + wn * 64 + nt * 8 + quad * 2;
            if (ncol < N) {
                float2 v0 = make_float2(acc[mt][nt][0], acc[mt][nt][1]);
                float2 v1 = make_float2(acc[mt][nt][2], acc[mt][nt][3]);
                *(float2*)(C + (size_t)mrow * N + ncol) = v0;
                *(float2*)(C + (size_t)(mrow + 8) * N + ncol) = v1;
            }
        }
    }
}

// ---------------------------------------------------------------------------
// RMSNorm
// ---------------------------------------------------------------------------
__global__ void rmsnorm_kernel(float* __restrict__ X, const float* __restrict__ w, int N)
{
    const int row = blockIdx.x;
    float* x = X + (size_t)row * N;
    __shared__ float red[256];
    float ss = 0.f;
    for (int i = threadIdx.x; i < N; i += 256) { float v = x[i]; ss += v * v; }
    red[threadIdx.x] = ss;
    __syncthreads();
    for (int s = 128; s > 0; s >>= 1) {
        if (threadIdx.x < s) red[threadIdx.x] += red[threadIdx.x + s];
        __syncthreads();
    }
    const float scale = rsqrtf(red[0] / (float)N + 1e-5f);
    for (int i = threadIdx.x; i < N; i += 256) x[i] = x[i] * scale * w[i];
}

// ---------------------------------------------------------------------------
// Build Q/K/V (RoPE fused)
// ---------------------------------------------------------------------------
__global__ void build_q_kernel(const float* __restrict__ qn, const float* __restrict__ qr,
                               const float* __restrict__ fcos, const float* __restrict__ fsin,
                               float* __restrict__ Qo)
{
    const int idx = blockIdx.x * blockDim.x + threadIdx.x;
    const int total = B_ * H_ * S_ * DQK;
    if (idx >= total) return;
    const int d = idx % DQK;
    const int s = (idx / DQK) % S_;
    const int h = (idx / (DQK * S_)) % H_;
    const int b = idx / (DQK * S_ * H_);
    const int row = b * S_ + s;
    float val;
    if (d < DN) {
        val = qn[(size_t)row * (H_ * DN) + h * DN + d];
    } else {
        const int t = d - DN;
        const int i = t >> 1;
        const float* base = qr + (size_t)row * (H_ * DR) + h * DR + 2 * i;
        const float r = base[0], im = base[1];
        const float c = fcos[h * (DR / 2) + i], sn = fsin[h * (DR / 2) + i];
        val = (t & 1) ? (r * sn + im * c) : (r * c - im * sn);
    }
    Qo[idx] = val;
}

__global__ void build_k_kernel(const float* __restrict__ kn, const float* __restrict__ kr,
                               const float* __restrict__ fcos, const float* __restrict__ fsin,
                               float* __restrict__ Ko)
{
    const int idx = blockIdx.x * blockDim.x + threadIdx.x;
    const int total = B_ * H_ * S_ * DQK;
    if (idx >= total) return;
    const int d = idx % DQK;
    const int s = (idx / DQK) % S_;
    const int h = (idx / (DQK * S_)) % H_;
    const int b = idx / (DQK * S_ * H_);
    const int row = b * S_ + s;
    float val;
    if (d < DN) {
        val = kn[(size_t)row * (H_ * DN) + h * DN + d];
    } else {
        const int t = d - DN;
        const int i = t >> 1;
        const float* base = kr + (size_t)row * DR + 2 * i;
        const float r = base[0], im = base[1];
        const float c = fcos[h * (DR / 2) + i], sn = fsin[h * (DR / 2) + i];
        val = (t & 1) ? (r * sn + im * c) : (r * c - im * sn);
    }
    Ko[idx] = val;
}

__global__ void build_v_kernel(const float* __restrict__ vr, float* __restrict__ Vo)
{
    const int idx = blockIdx.x * blockDim.x + threadIdx.x;
    const int total = B_ * H_ * S_ * DV;
    if (idx >= total) return;
    const int d = idx % DV;
    const int s = (idx / DV) % S_;
    const int h = (idx / (DV * S_)) % H_;
    const int b = idx / (DV * S_ * H_);
    const int row = b * S_ + s;
    Vo[idx] = vr[(size_t)row * (H_ * DV) + h * DV + d] * 0.022097086912079608f;
}

// ---------------------------------------------------------------------------
// Tensor-core flash attention (tf32), causal. Tiles 64q x 64k, d=192 staged.
// QK^T: warps 4x2, warp tile 16x32.  PV: computed as O^T = V^T @ P^T so both
// operands load directly from row-major Vs/Ss (fragment loads are plain LDS).
// Smem strides 196/136/68 (all == 4 mod 32) -> conflict-free fragment reads.
// ---------------------------------------------------------------------------
#define AQS 196   // Qs/Ks row stride
#define AVS 136   // Vs row stride
#define ASS 68    // Ss row stride
#define ATT_SMEM_FLOATS (64*AQS + 64*AQS + 64*AVS + 64*ASS + 3*64)
#define ATT_SMEM_BYTES  (ATT_SMEM_FLOATS * 4)

__global__ __launch_bounds__(256)
void attn_tc_kernel(const float* __restrict__ Q, const float* __restrict__ K,
                    const float* __restrict__ V)
{
    extern __shared__ float sm[];
    float* Qs = sm;                      // [64][196]
    float* Ks = Qs + 64 * AQS;           // [64][196]
    float* Vs = Ks + 64 * AQS;           // [64][136]  (row = k-pos j, col = d)
    float* Ss = Vs + 64 * AVS;           // [64][68]   (row = q, col = j)
    float* m_s = Ss + 64 * ASS;
    float* l_s = m_s + 64;
    float* a_s = l_s + 64;

    const int tid  = threadIdx.x;
    const int lane = tid & 31;
    const int wid  = tid >> 5;           // 0..7
    const int grp  = lane >> 2;          // 0..7
    const int quad = lane & 3;           // 0..3
    const int wm   = wid & 3;            // QK: q-row block (16 rows)
    const int wn   = wid >> 2;           // QK: k-col block (32 cols)
    const int d0   = wid * 16;           // PV: d-row block of O^T

    const int b = blockIdx.z, h = blockIdx.y;
    const int qt = (int)gridDim.x - 1 - (int)blockIdx.x;
    const int q0 = qt * 64;

    const float* Qg = Q + ((size_t)(b * H_ + h) * S_ + q0) * DQK;
    const float* Kg = K + ((size_t)(b * H_ + h) * S_) * DQK;
    const float* Vg = V + ((size_t)(b * H_ + h) * S_) * DV;

    // Q tile
    for (int idx = tid * 4; idx < 64 * DQK; idx += 1024) {
        const float4 v = *(const float4*)(Qg + idx);
        const int r = idx / DQK, c = idx % DQK;
        *(float4*)(Qs + r * AQS + c) = v;
    }
    if (tid < 64) { m_s[tid] = -1e30f; l_s[tid] = 0.f; }

    float oacc[8][4];                    // O^T: rows d0+grp(+8), cols q = nt*8+quad*2(+1)
#pragma unroll
    for (int nt = 0; nt < 8; ++nt)
#pragma unroll
        for (int i = 0; i < 4; ++i) oacc[nt][i] = 0.f;

    const float scale = 0.07216878364870322f;   // 1/sqrt(192)

    for (int kt = 0; kt <= qt; ++kt) {
        const int k0 = kt * 64;
        __syncthreads();
        for (int idx = tid * 4; idx < 64 * DQK; idx += 1024) {
            const float4 v = *(const float4*)(Kg + (size_t)k0 * DQK + idx);
            const int r = idx / DQK, c = idx % DQK;
            *(float4*)(Ks + r * AQS + c) = v;
        }
        for (int idx = tid * 4; idx < 64 * DV; idx += 1024) {
            const float4 v = *(const float4*)(Vg + (size_t)k0 * DV + idx);
            const int r = idx / DV, c = idx % DV;
            *(float4*)(Vs + r * AVS + c) = v;
        }
        __syncthreads();

        // ---- S = Q K^T (tf32 mma) ----
        float sacc[4][4];
#pragma unroll
        for (int nt = 0; nt < 4; ++nt)
#pragma unroll
            for (int i = 0; i < 4; ++i) sacc[nt][i] = 0.f;

        const int mrow = wm * 16 + grp;
#pragma unroll 4
        for (int kk = 0; kk < DQK; kk += 8) {
            uint32_t afr[4];
            afr[0] = f2tf32(Qs[(mrow    ) * AQS + kk + quad    ]);
            afr[1] = f2tf32(Qs[(mrow + 8) * AQS + kk + quad    ]);
            afr[2] = f2tf32(Qs[(mrow    ) * AQS + kk + quad + 4]);
            afr[3] = f2tf32(Qs[(mrow + 8) * AQS + kk + quad + 4]);
#pragma unroll
            for (int nt = 0; nt < 4; ++nt) {
                const int ncol = wn * 32 + nt * 8 + grp;
                uint32_t bfr[2];
                bfr[0] = f2tf32(Ks[ncol * AQS + kk + quad    ]);
                bfr[1] = f2tf32(Ks[ncol * AQS + kk + quad + 4]);
                mma_tf32(sacc[nt], afr, bfr);
            }
        }
        // scale + causal mask + store S
#pragma unroll
        for (int nt = 0; nt < 4; ++nt) {
            const int col = wn * 32 + nt * 8 + quad * 2;
            const int ki0 = k0 + col, ki1 = k0 + col + 1;
            const int qiA = q0 + mrow, qiB = q0 + mrow + 8;
            float v0 = sacc[nt][0] * scale; if (ki0 > qiA) v0 = -1e30f;
            float v1 = sacc[nt][1] * scale; if (ki1 > qiA) v1 = -1e30f;
            float v2 = sacc[nt][2] * scale; if (ki0 > qiB) v2 = -1e30f;
            float v3 = sacc[nt][3] * scale; if (ki1 > qiB) v3 = -1e30f;
            *(float2*)(Ss + (mrow    ) * ASS + col) = make_float2(v0, v1);
            *(float2*)(Ss + (mrow + 8) * ASS + col) = make_float2(v2, v3);
        }
        __syncthreads();

        // ---- online softmax ----
        if (tid < 64) {
            float* row = Ss + tid * ASS;
            const float mold = m_s[tid];
            float mx = mold;
#pragma unroll 8
            for (int j = 0; j < 64; ++j) mx = fmaxf(mx, row[j]);
            const float alpha = __expf(mold - mx);
            float l = l_s[tid] * alpha;
#pragma unroll 8
            for (int j = 0; j < 64; ++j) { const float p = __expf(row[j] - mx); row[j] = p; l += p; }
            m_s[tid] = mx; l_s[tid] = l; a_s[tid] = alpha;
        }
        __syncthreads();

        // ---- rescale O^T accumulators by alpha(q) ----
#pragma unroll
        for (int nt = 0; nt < 8; ++nt) {
            const int qb = nt * 8 + quad * 2;
            const float al0 = a_s[qb], al1 = a_s[qb + 1];
            oacc[nt][0] *= al0; oacc[nt][1] *= al1;
            oacc[nt][2] *= al0; oacc[nt][3] *= al1;
        }

        // ---- O^T += V^T @ P^T (tf32 mma) ----
#pragma unroll
        for (int kk = 0; kk < 64; kk += 8) {
            uint32_t afr[4];
            afr[0] = f2tf32(Vs[(kk + quad    ) * AVS + d0 + grp    ]);
            afr[1] = f2tf32(Vs[(kk + quad    ) * AVS + d0 + grp + 8]);
            afr[2] = f2tf32(Vs[(kk + quad + 4) * AVS + d0 + grp    ]);
            afr[3] = f2tf32(Vs[(kk + quad + 4) * AVS + d0 + grp + 8]);
#pragma unroll
            for (int nt = 0; nt < 8; ++nt) {
                const int qrow = nt * 8 + grp;
                uint32_t bfr[2];
                bfr[0] = f2tf32(Ss[qrow * ASS + kk + quad    ]);
                bfr[1] = f2tf32(Ss[qrow * ASS + kk + quad + 4]);
                mma_tf32(oacc[nt], afr, bfr);
            }
        }
    }
    __syncthreads();

    // stage O^T -> Os[q][d] in smem (reuse Qs region), then coalesced store
    float* Os = Qs;   // [64][AVS]
#pragma unroll
    for (int nt = 0; nt < 8; ++nt) {
        const int q = nt * 8 + quad * 2;
        const int d = d0 + grp;
        Os[(q    ) * AVS + d    ] = oacc[nt][0];
        Os[(q + 1) * AVS + d    ] = oacc[nt][1];
        Os[(q    ) * AVS + d + 8] = oacc[nt][2];
        Os[(q + 1) * AVS + d + 8] = oacc[nt][3];
    }
    __syncthreads();

    for (int idx = tid * 4; idx < 64 * DV; idx += 1024) {
        const int q = idx / DV, d = idx % DV;
        const float linv = 1.f / l_s[q];
        float4 v = *(const float4*)(Os + q * AVS + d);
        v.x *= linv; v.y *= linv; v.z *= linv; v.w *= linv;
        *(float4*)(g_O + (((size_t)(b * S_ + q0 + q)) * H_ + h) * DV + d) = v;
    }
}

// ---------------------------------------------------------------------------
// Host launcher
// ---------------------------------------------------------------------------
extern "C" void kernel_launch(void* const* d_in, const int* in_sizes, int n_in,
                              void* d_out, int out_size)
{
    (void)in_sizes; (void)n_in; (void)out_size;
    const float* x        = (const float*)d_in[0];
    const float* fcos     = (const float*)d_in[2];
    const float* fsin     = (const float*)d_in[3];
    const float* w_cq     = (const float*)d_in[4];
    const float* q_norm_w = (const float*)d_in[5];
    const float* w_dq_n   = (const float*)d_in[6];
    const float* w_dq_r   = (const float*)d_in[7];
    const float* w_ckv    = (const float*)d_in[8];
    const float* kv_norm_w= (const float*)d_in[9];
    const float* w_dk_n   = (const float*)d_in[10];
    const float* w_dv     = (const float*)d_in[11];
    const float* w_k_rope = (const float*)d_in[12];
    const float* w_proj   = (const float*)d_in[13];
    float* out = (float*)d_out;

    float *nq, *qn, *qr, *nkv, *kn, *vr, *kr, *Q, *K, *V, *O;
    cudaGetSymbolAddress((void**)&nq,  g_nq);
    cudaGetSymbolAddress((void**)&qn,  g_qn);
    cudaGetSymbolAddress((void**)&qr,  g_qr);
    cudaGetSymbolAddress((void**)&nkv, g_nkv);
    cudaGetSymbolAddress((void**)&kn,  g_kn);
    cudaGetSymbolAddress((void**)&vr,  g_vr);
    cudaGetSymbolAddress((void**)&kr,  g_kr);
    cudaGetSymbolAddress((void**)&Q,   g_Q);
    cudaGetSymbolAddress((void**)&K,   g_K);
    cudaGetSymbolAddress((void**)&V,   g_V);
    cudaGetSymbolAddress((void**)&O,   g_O);

    // --- projections + norms (tf32 tensor cores) ---
    gemm_tf32_kernel<<<dim3(RQ / 128, BS / 128), 256>>>(x, w_cq, nq, BS, RQ, D_);
    rmsnorm_kernel<<<BS, 256>>>(nq, q_norm_w, RQ);
    gemm_tf32_kernel<<<dim3((H_ * DN) / 128, BS / 128), 256>>>(nq, w_dq_n, qn, BS, H_ * DN, RQ);
    gemm_tf32_kernel<<<dim3((H_ * DR) / 128, BS / 128), 256>>>(nq, w_dq_r, qr, BS, H_ * DR, RQ);
    gemm_tf32_kernel<<<dim3(RKV / 128, BS / 128), 256>>>(x, w_ckv, nkv, BS, RKV, D_);
    rmsnorm_kernel<<<BS, 256>>>(nkv, kv_norm_w, RKV);
    gemm_tf32_kernel<<<dim3((H_ * DN) / 128, BS / 128), 256>>>(nkv, w_dk_n, kn, BS, H_ * DN, RKV);
    gemm_tf32_kernel<<<dim3((H_ * DV) / 128, BS / 128), 256>>>(nkv, w_dv, vr, BS, H_ * DV, RKV);
    gemm_tf32_kernel<<<dim3(1, BS / 128), 256>>>(x, w_k_rope, kr, BS, DR, D_);

    // --- assemble Q/K/V ---
    {
        const int tq = B_ * H_ * S_ * DQK;
        build_q_kernel<<<(tq + 255) / 256, 256>>>(qn, qr, fcos, fsin, Q);
        build_k_kernel<<<(tq + 255) / 256, 256>>>(kn, kr, fcos, fsin, K);
        const int tv = B_ * H_ * S_ * DV;
        build_v_kernel<<<(tv + 255) / 256, 256>>>(vr, V);
    }

    // --- tensor-core flash attention ---
    cudaFuncSetAttribute(attn_tc_kernel, cudaFuncAttributeMaxDynamicSharedMemorySize, ATT_SMEM_BYTES);
    attn_tc_kernel<<<dim3(S_ / 64, H_, B_), 256, ATT_SMEM_BYTES>>>(Q, K, V);

    // --- output projection ---
    gemm_tf32_kernel<<<dim3(D_ / 128, BS / 128), 256>>>(O, w_proj, out, BS, D_, D_);
}

// round 14
// speedup vs baseline: 2.9538x; 1.0830x over previous
#include <cuda_runtime.h>
#include <cstdint>

// Problem constants
#define B_   2
#define S_   2048
#define D_   2048
#define H_   16
#define DN   128
#define DR   64
#define DV   128
#define RQ   1536
#define RKV  512
#define DQK  192
#define BS   (B_ * S_)

// ---------------------------------------------------------------------------
// Scratch
// ---------------------------------------------------------------------------
__device__ float g_nq [BS * RQ];
__device__ float g_qn [BS * H_ * DN];
__device__ float g_qr [BS * H_ * DR];
__device__ float g_nkv[BS * RKV];
__device__ float g_kn [BS * H_ * DN];
__device__ float g_vr [BS * H_ * DV];
__device__ float g_kr [BS * DR];
__device__ float g_Q  [B_ * H_ * S_ * DQK];
__device__ float g_K  [B_ * H_ * S_ * DQK];
__device__ float g_V  [B_ * H_ * S_ * DV];
__device__ float g_O  [BS * H_ * DV];

// ---------------------------------------------------------------------------
// tf32 helpers
// ---------------------------------------------------------------------------
__device__ __forceinline__ void cp_async16(uint32_t dst, const void* src, int src_bytes) {
    asm volatile("cp.async.ca.shared.global [%0], [%1], 16, %2;\n"
                 :: "r"(dst), "l"(src), "r"(src_bytes));
}
__device__ __forceinline__ uint32_t f2tf32(float f) {
    uint32_t r;
    asm("cvt.rna.tf32.f32 %0, %1;" : "=r"(r) : "f"(f));
    return r;
}
__device__ __forceinline__ void mma_tf32(float* c, const uint32_t* a, const uint32_t* b) {
    asm volatile(
        "mma.sync.aligned.m16n8k8.row.col.f32.tf32.tf32.f32 "
        "{%0,%1,%2,%3}, {%4,%5,%6,%7}, {%8,%9}, {%0,%1,%2,%3};"
        : "+f"(c[0]), "+f"(c[1]), "+f"(c[2]), "+f"(c[3])
        : "r"(a[0]), "r"(a[1]), "r"(a[2]), "r"(a[3]), "r"(b[0]), "r"(b[1]));
}

// ---------------------------------------------------------------------------
// tf32 tensor-core GEMM (unchanged)
// ---------------------------------------------------------------------------
#define ASTRIDE 20
#define BSTRIDE 136

__global__ __launch_bounds__(256)
void gemm_tf32_kernel(const float* __restrict__ A, const float* __restrict__ B,
                      float* __restrict__ C, int M, int N, int K)
{
    __shared__ float As[2][128][ASTRIDE];
    __shared__ float Bs[2][16][BSTRIDE];

    const int tid  = threadIdx.x;
    const int lane = tid & 31;
    const int wid  = tid >> 5;
    const int wm   = wid & 3;
    const int wn   = wid >> 2;
    const int grp  = lane >> 2;
    const int quad = lane & 3;

    const int m0 = blockIdx.y * 128;
    const int n0 = blockIdx.x * 128;

    const int ar0 = tid >> 2;
    const int ac0 = (tid & 3) * 4;
    const int br0 = tid >> 5;
    const int bc0 = (tid & 31) * 4;

    uint32_t sAs, sBs;
    { uint32_t base; asm("{ .reg .u64 t; cvta.to.shared.u64 t, %1; cvt.u32.u64 %0, t; }"
                         : "=r"(base) : "l"((void*)&As[0][0][0])); sAs = base; }
    { uint32_t base; asm("{ .reg .u64 t; cvta.to.shared.u64 t, %1; cvt.u32.u64 %0, t; }"
                         : "=r"(base) : "l"((void*)&Bs[0][0][0])); sBs = base; }

    const int ntiles = K / 16;

    auto load_stage = [&](int kt, int s) {
        const int k0 = kt * 16;
        {
            const float* src = A + (size_t)(m0 + ar0) * K + k0 + ac0;
            uint32_t dst = sAs + ((s * 128 + ar0) * ASTRIDE + ac0) * 4;
            cp_async16(dst, src, 16);
            const float* src2 = src + (size_t)64 * K;
            uint32_t dst2 = dst + 64 * ASTRIDE * 4;
            cp_async16(dst2, src2, 16);
        }
        {
            const int col = n0 + bc0;
            const int ok = (col < N) ? 16 : 0;
            const float* src = B + (size_t)(k0 + br0) * N + (ok ? col : 0);
            uint32_t dst = sBs + ((s * 16 + br0) * BSTRIDE + bc0) * 4;
            cp_async16(dst, src, ok);
            const float* src2 = src + (size_t)8 * N;
            uint32_t dst2 = dst + 8 * BSTRIDE * 4;
            cp_async16(dst2, src2, ok);
        }
    };

    float acc[2][8][4];
#pragma unroll
    for (int mt = 0; mt < 2; ++mt)
#pragma unroll
        for (int nt = 0; nt < 8; ++nt)
#pragma unroll
            for (int i = 0; i < 4; ++i) acc[mt][nt][i] = 0.f;

    load_stage(0, 0);
    asm volatile("cp.async.commit_group;\n");

    for (int kt = 0; kt < ntiles; ++kt) {
        const int s = kt & 1;
        if (kt + 1 < ntiles) load_stage(kt + 1, (kt + 1) & 1);
        asm volatile("cp.async.commit_group;\n");
        asm volatile("cp.async.wait_group 1;\n");
        __syncthreads();

#pragma unroll
        for (int kk = 0; kk < 16; kk += 8) {
            uint32_t afr[2][4];
#pragma unroll
            for (int mt = 0; mt < 2; ++mt) {
                const int mrow = wm * 32 + mt * 16 + grp;
                afr[mt][0] = f2tf32(As[s][mrow    ][kk + quad    ]);
                afr[mt][1] = f2tf32(As[s][mrow + 8][kk + quad    ]);
                afr[mt][2] = f2tf32(As[s][mrow    ][kk + quad + 4]);
                afr[mt][3] = f2tf32(As[s][mrow + 8][kk + quad + 4]);
            }
            uint32_t bfr[8][2];
#pragma unroll
            for (int nt = 0; nt < 8; ++nt) {
                const int ncol = wn * 64 + nt * 8 + grp;
                bfr[nt][0] = f2tf32(Bs[s][kk + quad    ][ncol]);
                bfr[nt][1] = f2tf32(Bs[s][kk + quad + 4][ncol]);
            }
#pragma unroll
            for (int mt = 0; mt < 2; ++mt)
#pragma unroll
                for (int nt = 0; nt < 8; ++nt)
                    mma_tf32(acc[mt][nt], afr[mt], bfr[nt]);
        }
        __syncthreads();
    }
    asm volatile("cp.async.wait_group 0;\n");

#pragma unroll
    for (int mt = 0; mt < 2; ++mt) {
        const int mrow = m0 + wm * 32 + mt * 16 + grp;
#pragma unroll
        for (int nt = 0; nt < 8; ++nt) {
            const int ncol = n0 + wn * 64 + nt * 8 + quad * 2;
            if (ncol < N) {
                float2 v0 = make_float2(acc[mt][nt][0], acc[mt][nt][1]);
                float2 v1 = make_float2(acc[mt][nt][2], acc[mt][nt][3]);
                *(float2*)(C + (size_t)mrow * N + ncol) = v0;
                *(float2*)(C + (size_t)(mrow + 8) * N + ncol) = v1;
            }
        }
    }
}

// ---------------------------------------------------------------------------
// RMSNorm
// ---------------------------------------------------------------------------
__global__ void rmsnorm_kernel(float* __restrict__ X, const float* __restrict__ w, int N)
{
    const int row = blockIdx.x;
    float* x = X + (size_t)row * N;
    __shared__ float red[256];
    float ss = 0.f;
    for (int i = threadIdx.x; i < N; i += 256) { float v = x[i]; ss += v * v; }
    red[threadIdx.x] = ss;
    __syncthreads();
    for (int s = 128; s > 0; s >>= 1) {
        if (threadIdx.x < s) red[threadIdx.x] += red[threadIdx.x + s];
        __syncthreads();
    }
    const float scale = rsqrtf(red[0] / (float)N + 1e-5f);
    for (int i = threadIdx.x; i < N; i += 256) x[i] = x[i] * scale * w[i];
}

// ---------------------------------------------------------------------------
// Build Q/K/V (RoPE fused)
// ---------------------------------------------------------------------------
__global__ void build_q_kernel(const float* __restrict__ qn, const float* __restrict__ qr,
                               const float* __restrict__ fcos, const float* __restrict__ fsin,
                               float* __restrict__ Qo)
{
    const int idx = blockIdx.x * blockDim.x + threadIdx.x;
    const int total = B_ * H_ * S_ * DQK;
    if (idx >= total) return;
    const int d = idx % DQK;
    const int s = (idx / DQK) % S_;
    const int h = (idx / (DQK * S_)) % H_;
    const int b = idx / (DQK * S_ * H_);
    const int row = b * S_ + s;
    float val;
    if (d < DN) {
        val = qn[(size_t)row * (H_ * DN) + h * DN + d];
    } else {
        const int t = d - DN;
        const int i = t >> 1;
        const float* base = qr + (size_t)row * (H_ * DR) + h * DR + 2 * i;
        const float r = base[0], im = base[1];
        const float c = fcos[h * (DR / 2) + i], sn = fsin[h * (DR / 2) + i];
        val = (t & 1) ? (r * sn + im * c) : (r * c - im * sn);
    }
    Qo[idx] = val;
}

__global__ void build_k_kernel(const float* __restrict__ kn, const float* __restrict__ kr,
                               const float* __restrict__ fcos, const float* __restrict__ fsin,
                               float* __restrict__ Ko)
{
    const int idx = blockIdx.x * blockDim.x + threadIdx.x;
    const int total = B_ * H_ * S_ * DQK;
    if (idx >= total) return;
    const int d = idx % DQK;
    const int s = (idx / DQK) % S_;
    const int h = (idx / (DQK * S_)) % H_;
    const int b = idx / (DQK * S_ * H_);
    const int row = b * S_ + s;
    float val;
    if (d < DN) {
        val = kn[(size_t)row * (H_ * DN) + h * DN + d];
    } else {
        const int t = d - DN;
        const int i = t >> 1;
        const float* base = kr + (size_t)row * DR + 2 * i;
        const float r = base[0], im = base[1];
        const float c = fcos[h * (DR / 2) + i], sn = fsin[h * (DR / 2) + i];
        val = (t & 1) ? (r * sn + im * c) : (r * c - im * sn);
    }
    Ko[idx] = val;
}

__global__ void build_v_kernel(const float* __restrict__ vr, float* __restrict__ Vo)
{
    const int idx = blockIdx.x * blockDim.x + threadIdx.x;
    const int total = B_ * H_ * S_ * DV;
    if (idx >= total) return;
    const int d = idx % DV;
    const int s = (idx / DV) % S_;
    const int h = (idx / (DV * S_)) % H_;
    const int b = idx / (DV * S_ * H_);
    const int row = b * S_ + s;
    Vo[idx] = vr[(size_t)row * (H_ * DV) + h * DV + d] * 0.022097086912079608f;
}

// ---------------------------------------------------------------------------
// Tensor-core flash attention v2 (tf32), causal.
// Changes vs v1: Q/K/V stored in smem as PRE-CONVERTED tf32 bit patterns
// (fragment loads are raw LDS, no cvt in the mma loops); softmax runs on all
// 256 threads (8 warps x 8 rows, 4 lanes/row, stride-4 cols, shfl quad
// reductions) and writes probs back already tf32-converted.
// Numerically bit-identical to v1 (cvt is idempotent).
// ---------------------------------------------------------------------------
#define AQS 196   // Qs/Ks row stride
#define AVS 136   // Vs row stride
#define ASS 68    // Ss row stride
#define ATT_SMEM_FLOATS (64*AQS + 64*AQS + 64*AVS + 64*ASS + 3*64)
#define ATT_SMEM_BYTES  (ATT_SMEM_FLOATS * 4)

__global__ __launch_bounds__(256)
void attn_tc_kernel(const float* __restrict__ Q, const float* __restrict__ K,
                    const float* __restrict__ V)
{
    extern __shared__ float sm[];
    float* Qs = sm;                      // [64][196]  tf32 bits
    float* Ks = Qs + 64 * AQS;           // [64][196]  tf32 bits
    float* Vs = Ks + 64 * AQS;           // [64][136]  tf32 bits (row j, col d)
    float* Ss = Vs + 64 * AVS;           // [64][68]   scores (float) -> probs (tf32 bits)
    float* m_s = Ss + 64 * ASS;
    float* l_s = m_s + 64;
    float* a_s = l_s + 64;

    const int tid  = threadIdx.x;
    const int lane = tid & 31;
    const int wid  = tid >> 5;           // 0..7
    const int grp  = lane >> 2;          // 0..7
    const int quad = lane & 3;           // 0..3
    const int wm   = wid & 3;            // QK: q-row block
    const int wn   = wid >> 2;           // QK: k-col block
    const int d0   = wid * 16;           // PV: d-row block of O^T

    const int b = blockIdx.z, h = blockIdx.y;
    const int qt = (int)gridDim.x - 1 - (int)blockIdx.x;
    const int q0 = qt * 64;

    const float* Qg = Q + ((size_t)(b * H_ + h) * S_ + q0) * DQK;
    const float* Kg = K + ((size_t)(b * H_ + h) * S_) * DQK;
    const float* Vg = V + ((size_t)(b * H_ + h) * S_) * DV;

    // Q tile: convert to tf32 bits once
    for (int idx = tid * 4; idx < 64 * DQK; idx += 1024) {
        const float4 v = *(const float4*)(Qg + idx);
        const int r = idx / DQK, c = idx % DQK;
        float4 w;
        w.x = __uint_as_float(f2tf32(v.x));
        w.y = __uint_as_float(f2tf32(v.y));
        w.z = __uint_as_float(f2tf32(v.z));
        w.w = __uint_as_float(f2tf32(v.w));
        *(float4*)(Qs + r * AQS + c) = w;
    }
    if (tid < 64) { m_s[tid] = -1e30f; l_s[tid] = 0.f; }

    float oacc[8][4];
#pragma unroll
    for (int nt = 0; nt < 8; ++nt)
#pragma unroll
        for (int i = 0; i < 4; ++i) oacc[nt][i] = 0.f;

    const float scale = 0.07216878364870322f;   // 1/sqrt(192)

    for (int kt = 0; kt <= qt; ++kt) {
        const int k0 = kt * 64;
        __syncthreads();
        for (int idx = tid * 4; idx < 64 * DQK; idx += 1024) {
            const float4 v = *(const float4*)(Kg + (size_t)k0 * DQK + idx);
            const int r = idx / DQK, c = idx % DQK;
            float4 w;
            w.x = __uint_as_float(f2tf32(v.x));
            w.y = __uint_as_float(f2tf32(v.y));
            w.z = __uint_as_float(f2tf32(v.z));
            w.w = __uint_as_float(f2tf32(v.w));
            *(float4*)(Ks + r * AQS + c) = w;
        }
        for (int idx = tid * 4; idx < 64 * DV; idx += 1024) {
            const float4 v = *(const float4*)(Vg + (size_t)k0 * DV + idx);
            const int r = idx / DV, c = idx % DV;
            float4 w;
            w.x = __uint_as_float(f2tf32(v.x));
            w.y = __uint_as_float(f2tf32(v.y));
            w.z = __uint_as_float(f2tf32(v.z));
            w.w = __uint_as_float(f2tf32(v.w));
            *(float4*)(Vs + r * AVS + c) = w;
        }
        __syncthreads();

        // ---- S = Q K^T (tf32 mma, operands pre-converted) ----
        float sacc[4][4];
#pragma unroll
        for (int nt = 0; nt < 4; ++nt)
#pragma unroll
            for (int i = 0; i < 4; ++i) sacc[nt][i] = 0.f;

        const int mrow = wm * 16 + grp;
#pragma unroll 4
        for (int kk = 0; kk < DQK; kk += 8) {
            uint32_t afr[4];
            afr[0] = __float_as_uint(Qs[(mrow    ) * AQS + kk + quad    ]);
            afr[1] = __float_as_uint(Qs[(mrow + 8) * AQS + kk + quad    ]);
            afr[2] = __float_as_uint(Qs[(mrow    ) * AQS + kk + quad + 4]);
            afr[3] = __float_as_uint(Qs[(mrow + 8) * AQS + kk + quad + 4]);
#pragma unroll
            for (int nt = 0; nt < 4; ++nt) {
                const int ncol = wn * 32 + nt * 8 + grp;
                uint32_t bfr[2];
                bfr[0] = __float_as_uint(Ks[ncol * AQS + kk + quad    ]);
                bfr[1] = __float_as_uint(Ks[ncol * AQS + kk + quad + 4]);
                mma_tf32(sacc[nt], afr, bfr);
            }
        }
        // scale + causal mask + store S (float)
#pragma unroll
        for (int nt = 0; nt < 4; ++nt) {
            const int col = wn * 32 + nt * 8 + quad * 2;
            const int ki0 = k0 + col, ki1 = k0 + col + 1;
            const int qiA = q0 + mrow, qiB = q0 + mrow + 8;
            float v0 = sacc[nt][0] * scale; if (ki0 > qiA) v0 = -1e30f;
            float v1 = sacc[nt][1] * scale; if (ki1 > qiA) v1 = -1e30f;
            float v2 = sacc[nt][2] * scale; if (ki0 > qiB) v2 = -1e30f;
            float v3 = sacc[nt][3] * scale; if (ki1 > qiB) v3 = -1e30f;
            *(float2*)(Ss + (mrow    ) * ASS + col) = make_float2(v0, v1);
            *(float2*)(Ss + (mrow + 8) * ASS + col) = make_float2(v2, v3);
        }
        __syncthreads();

        // ---- online softmax: 8 warps x 8 rows, 4 lanes/row, stride-4 cols ----
        {
            const int row = wid * 8 + (lane >> 2);       // 0..63
            const int q4  = lane & 3;                    // column phase 0..3
            float* rp = Ss + row * ASS;
            const float mold = m_s[row];
            float mx = mold;
#pragma unroll
            for (int j = 0; j < 16; ++j) mx = fmaxf(mx, rp[4 * j + q4]);
            mx = fmaxf(mx, __shfl_xor_sync(0xffffffffu, mx, 1));
            mx = fmaxf(mx, __shfl_xor_sync(0xffffffffu, mx, 2));
            float psum = 0.f;
#pragma unroll
            for (int j = 0; j < 16; ++j) {
                const float p = __expf(rp[4 * j + q4] - mx);
                rp[4 * j + q4] = __uint_as_float(f2tf32(p));   // store tf32 probs
                psum += p;
            }
            psum += __shfl_xor_sync(0xffffffffu, psum, 1);
            psum += __shfl_xor_sync(0xffffffffu, psum, 2);
            if (q4 == 0) {
                const float alpha = __expf(mold - mx);
                l_s[row] = l_s[row] * alpha + psum;
                m_s[row] = mx;
                a_s[row] = alpha;
            }
        }
        __syncthreads();

        // ---- rescale O^T accumulators by alpha(q) ----
#pragma unroll
        for (int nt = 0; nt < 8; ++nt) {
            const int qb = nt * 8 + quad * 2;
            const float al0 = a_s[qb], al1 = a_s[qb + 1];
            oacc[nt][0] *= al0; oacc[nt][1] *= al1;
            oacc[nt][2] *= al0; oacc[nt][3] *= al1;
        }

        // ---- O^T += V^T @ P^T (operands pre-converted) ----
#pragma unroll
        for (int kk = 0; kk < 64; kk += 8) {
            uint32_t afr[4];
            afr[0] = __float_as_uint(Vs[(kk + quad    ) * AVS + d0 + grp    ]);
            afr[1] = __float_as_uint(Vs[(kk + quad    ) * AVS + d0 + grp + 8]);
            afr[2] = __float_as_uint(Vs[(kk + quad + 4) * AVS + d0 + grp    ]);
            afr[3] = __float_as_uint(Vs[(kk + quad + 4) * AVS + d0 + grp + 8]);
#pragma unroll
            for (int nt = 0; nt < 8; ++nt) {
                const int qrow = nt * 8 + grp;
                uint32_t bfr[2];
                bfr[0] = __float_as_uint(Ss[qrow * ASS + kk + quad    ]);
                bfr[1] = __float_as_uint(Ss[qrow * ASS + kk + quad + 4]);
                mma_tf32(oacc[nt], afr, bfr);
            }
        }
    }
    __syncthreads();

    // stage O^T -> Os[q][d] in smem (reuse Qs region), then coalesced store
    float* Os = Qs;   // [64][AVS]
#pragma unroll
    for (int nt = 0; nt < 8; ++nt) {
        const int q = nt * 8 + quad * 2;
        const int d = d0 + grp;
        Os[(q    ) * AVS + d    ] = oacc[nt][0];
        Os[(q + 1) * AVS + d    ] = oacc[nt][1];
        Os[(q    ) * AVS + d + 8] = oacc[nt][2];
        Os[(q + 1) * AVS + d + 8] = oacc[nt][3];
    }
    __syncthreads();

    for (int idx = tid * 4; idx < 64 * DV; idx += 1024) {
        const int q = idx / DV, d = idx % DV;
        const float linv = 1.f / l_s[q];
        float4 v = *(const float4*)(Os + q * AVS + d);
        v.x *= linv; v.y *= linv; v.z *= linv; v.w *= linv;
        *(float4*)(g_O + (((size_t)(b * S_ + q0 + q)) * H_ + h) * DV + d) = v;
    }
}

// ---------------------------------------------------------------------------
// Host launcher
// ---------------------------------------------------------------------------
extern "C" void kernel_launch(void* const* d_in, const int* in_sizes, int n_in,
                              void* d_out, int out_size)
{
    (void)in_sizes; (void)n_in; (void)out_size;
    const float* x        = (const float*)d_in[0];
    const float* fcos     = (const float*)d_in[2];
    const float* fsin     = (const float*)d_in[3];
    const float* w_cq     = (const float*)d_in[4];
    const float* q_norm_w = (const float*)d_in[5];
    const float* w_dq_n   = (const float*)d_in[6];
    const float* w_dq_r   = (const float*)d_in[7];
    const float* w_ckv    = (const float*)d_in[8];
    const float* kv_norm_w= (const float*)d_in[9];
    const float* w_dk_n   = (const float*)d_in[10];
    const float* w_dv     = (const float*)d_in[11];
    const float* w_k_rope = (const float*)d_in[12];
    const float* w_proj   = (const float*)d_in[13];
    float* out = (float*)d_out;

    float *nq, *qn, *qr, *nkv, *kn, *vr, *kr, *Q, *K, *V, *O;
    cudaGetSymbolAddress((void**)&nq,  g_nq);
    cudaGetSymbolAddress((void**)&qn,  g_qn);
    cudaGetSymbolAddress((void**)&qr,  g_qr);
    cudaGetSymbolAddress((void**)&nkv, g_nkv);
    cudaGetSymbolAddress((void**)&kn,  g_kn);
    cudaGetSymbolAddress((void**)&vr,  g_vr);
    cudaGetSymbolAddress((void**)&kr,  g_kr);
    cudaGetSymbolAddress((void**)&Q,   g_Q);
    cudaGetSymbolAddress((void**)&K,   g_K);
    cudaGetSymbolAddress((void**)&V,   g_V);
    cudaGetSymbolAddress((void**)&O,   g_O);

    // --- projections + norms (tf32 tensor cores) ---
    gemm_tf32_kernel<<<dim3(RQ / 128, BS / 128), 256>>>(x, w_cq, nq, BS, RQ, D_);
    rmsnorm_kernel<<<BS, 256>>>(nq, q_norm_w, RQ);
    gemm_tf32_kernel<<<dim3((H_ * DN) / 128, BS / 128), 256>>>(nq, w_dq_n, qn, BS, H_ * DN, RQ);
    gemm_tf32_kernel<<<dim3((H_ * DR) / 128, BS / 128), 256>>>(nq, w_dq_r, qr, BS, H_ * DR, RQ);
    gemm_tf32_kernel<<<dim3(RKV / 128, BS / 128), 256>>>(x, w_ckv, nkv, BS, RKV, D_);
    rmsnorm_kernel<<<BS, 256>>>(nkv, kv_norm_w, RKV);
    gemm_tf32_kernel<<<dim3((H_ * DN) / 128, BS / 128), 256>>>(nkv, w_dk_n, kn, BS, H_ * DN, RKV);
    gemm_tf32_kernel<<<dim3((H_ * DV) / 128, BS / 128), 256>>>(nkv, w_dv, vr, BS, H_ * DV, RKV);
    gemm_tf32_kernel<<<dim3(1, BS / 128), 256>>>(x, w_k_rope, kr, BS, DR, D_);

    // --- assemble Q/K/V ---
    {
        const int tq = B_ * H_ * S_ * DQK;
        build_q_kernel<<<(tq + 255) / 256, 256>>>(qn, qr, fcos, fsin, Q);
        build_k_kernel<<<(tq + 255) / 256, 256>>>(kn, kr, fcos, fsin, K);
        const int tv = B_ * H_ * S_ * DV;
        build_v_kernel<<<(tv + 255) / 256, 256>>>(vr, V);
    }

    // --- tensor-core flash attention v2 ---
    cudaFuncSetAttribute(attn_tc_kernel, cudaFuncAttributeMaxDynamicSharedMemorySize, ATT_SMEM_BYTES);
    attn_tc_kernel<<<dim3(S_ / 64, H_, B_), 256, ATT_SMEM_BYTES>>>(Q, K, V);

    // --- output projection ---
    gemm_tf32_kernel<<<dim3(D_ / 128, BS / 128), 256>>>(O, w_proj, out, BS, D_, D_);
}